// round 7
// baseline (speedup 1.0000x reference)
#include <cuda_runtime.h>
#include <cstdint>

// ROI max pooling (shapes fixed):
//   features: (B=4, C=256, H=50, W=50) fp32;  rois: (R=256,5) int32/int64-sniffed
//   out: (R=256, C=256, PH=7, PW=7) fp32
//
// 1) transpose -> g_featT[b][p][c] (channels contiguous), float4 + XOR swizzle.
// 2) pool: block = (r, ph), 4 warps = (zh half of C, pwg half of PW).
//    Lane owns 4 channels (float4). Warp owns 4 x-bins (pwg1: bin3 dups bin6,
//    max idempotent). Per row y: 4 clamped LDG.128 per bin, bins unrolled ->
//    8-16 independent loads in flight. Uniform control flow per warp.

#define RP_B  4
#define RP_C  256
#define RP_H  50
#define RP_W  50
#define RP_P  (RP_H * RP_W)   // 2500
#define RP_R  256
#define RP_PH 7
#define RP_PW 7
#define C4    (RP_C / 4)      // 64 float4 per position

__device__ float g_featT[RP_B * RP_P * RP_C];   // 10.24 MB scratch

__device__ __forceinline__ float4 f4max(float4 a, float4 b) {
    return make_float4(fmaxf(a.x, b.x), fmaxf(a.y, b.y),
                       fmaxf(a.z, b.z), fmaxf(a.w, b.w));
}

// ---------------- transpose: (B,C,P) -> (B,P,C) ----------------
__global__ __launch_bounds__(256)
void transpose_kernel(const float* __restrict__ feat)
{
    __shared__ float tile[32 * 128];
    const int b  = blockIdx.z;
    const int ct = blockIdx.y;                // 0..7
    const int pt = blockIdx.x;                // 0..19
    const int lane = threadIdx.x & 31;
    const int ty   = threadIdx.x >> 5;        // 0..7

    const int c0 = ct * 32;
    const int p0 = pt * 128;

    #pragma unroll
    for (int i = 0; i < 4; ++i) {
        const int cr = ty + 8 * i;
        const int p  = p0 + 4 * lane;
        if (p + 3 < RP_P) {
            const float4 v = __ldg((const float4*)(feat +
                                 ((size_t)(b * RP_C + c0 + cr)) * RP_P + p));
            *(float4*)&tile[cr * 128 + 4 * (lane ^ cr)] = v;
        } else {
            #pragma unroll
            for (int j = 0; j < 4; ++j) {
                const int pp = p + j;
                if (pp < RP_P)
                    tile[cr * 128 + 4 * (lane ^ cr) + j] =
                        __ldg(feat + ((size_t)(b * RP_C + c0 + cr)) * RP_P + pp);
            }
        }
    }
    __syncthreads();

    #pragma unroll
    for (int i = 0; i < 16; ++i) {
        const int p = i * 8 + ty;
        if (p0 + p < RP_P) {
            const int col = (p >> 2) ^ lane;
            g_featT[((size_t)b * RP_P + p0 + p) * RP_C + c0 + lane] =
                tile[lane * 128 + 4 * col + (p & 3)];
        }
    }
}

// ---------------- pool ----------------
__global__ __launch_bounds__(128, 8)
void roipool5_kernel(const int* __restrict__ rois32,
                     float* __restrict__ out)
{
    const int r    = blockIdx.x;
    const int ph   = blockIdx.y;
    const int wid  = threadIdx.x >> 5;        // 0..3
    const int lane = threadIdx.x & 31;
    const int zh   = wid & 1;                 // channel half
    const int pwg  = wid >> 1;                // pw group: 0 -> 0..3, 1 -> 4..6

    // dtype sniff (uniform, broadcast): int64 => all odd 32-bit words zero
    int odd = 0;
    #pragma unroll
    for (int i = 0; i < 16; ++i) odd |= __ldg(rois32 + 2 * i + 1);

    int b, x1, y1, w, h;
    if (odd == 0) {
        const int* rp = rois32 + r * 10;
        b  = __ldg(rp);
        x1 = __ldg(rp + 2) >> 4;  y1 = __ldg(rp + 4) >> 4;
        w  = (__ldg(rp + 6) >> 4) - x1 + 1;
        h  = (__ldg(rp + 8) >> 4) - y1 + 1;
    } else {
        const int* rp = rois32 + r * 5;
        b  = __ldg(rp);
        x1 = __ldg(rp + 1) >> 4;  y1 = __ldg(rp + 2) >> 4;
        w  = (__ldg(rp + 3) >> 4) - x1 + 1;
        h  = (__ldg(rp + 4) >> 4) - y1 + 1;
    }

    const int sh = y1 + (ph * h) / RP_PH;
    const int eh = y1 + (((ph + 1) * h + (RP_PH - 1)) / RP_PH);

    const int pw0 = pwg * 4;
    const int npw = pwg ? 3 : 4;

    // per-bin geometry (bin 3 of pwg=1 duplicates pw=6; idempotent)
    int colq[4], o1[4], o2[4], o3[4], bw[4];
    #pragma unroll
    for (int j = 0; j < 4; ++j) {
        const int pw = min(pw0 + j, RP_PW - 1);
        const int sw = x1 + (pw * w) / RP_PW;
        const int ew = x1 + (((pw + 1) * w + (RP_PW - 1)) / RP_PW);
        bw[j]   = ew - sw;                         // 1..8, warp-uniform
        colq[j] = sw * C4;
        o1[j]   = min(1, bw[j] - 1) * C4;
        o2[j]   = min(2, bw[j] - 1) * C4;
        o3[j]   = min(3, bw[j] - 1) * C4;
    }

    const float4* __restrict__ base =
        (const float4*)g_featT + ((size_t)b * RP_P) * C4 + zh * 32 + lane;

    const float NEG = __int_as_float(0xff800000);
    float4 acc[4];
    #pragma unroll
    for (int j = 0; j < 4; ++j) acc[j] = make_float4(NEG, NEG, NEG, NEG);

    const float4* rowp = base + sh * (RP_W * C4);
    for (int y = sh; y < eh; ++y) {
        // pair 1: bins 0,1
        #pragma unroll
        for (int j = 0; j < 2; ++j) {
            const float4* q = rowp + colq[j];
            float4 v0 = __ldg(q);
            float4 v1 = __ldg(q + o1[j]);
            float4 v2 = __ldg(q + o2[j]);
            float4 v3 = __ldg(q + o3[j]);
            for (int x = 4; x < bw[j]; ++x)        // rare, uniform
                v1 = f4max(v1, __ldg(q + x * C4));
            acc[j] = f4max(acc[j], f4max(f4max(v0, v1), f4max(v2, v3)));
        }
        // pair 2: bins 2,3
        #pragma unroll
        for (int j = 2; j < 4; ++j) {
            const float4* q = rowp + colq[j];
            float4 v0 = __ldg(q);
            float4 v1 = __ldg(q + o1[j]);
            float4 v2 = __ldg(q + o2[j]);
            float4 v3 = __ldg(q + o3[j]);
            for (int x = 4; x < bw[j]; ++x)
                v1 = f4max(v1, __ldg(q + x * C4));
            acc[j] = f4max(acc[j], f4max(f4max(v0, v1), f4max(v2, v3)));
        }
        rowp += RP_W * C4;
    }

    // store: lane owns channels c0..c0+3; each has npw contiguous floats
    const int c0 = zh * 128 + 4 * lane;
    float* __restrict__ ob =
        out + ((size_t)(r * RP_C + c0) * RP_PH + ph) * RP_PW + pw0;
    #pragma unroll
    for (int k = 0; k < 4; ++k) {
        float* o = ob + (size_t)k * (RP_PH * RP_PW);
        const float vx[4] = { k == 0 ? acc[0].x : k == 1 ? acc[0].y : k == 2 ? acc[0].z : acc[0].w,
                              k == 0 ? acc[1].x : k == 1 ? acc[1].y : k == 2 ? acc[1].z : acc[1].w,
                              k == 0 ? acc[2].x : k == 1 ? acc[2].y : k == 2 ? acc[2].z : acc[2].w,
                              k == 0 ? acc[3].x : k == 1 ? acc[3].y : k == 2 ? acc[3].z : acc[3].w };
        o[0] = vx[0];
        o[1] = vx[1];
        o[2] = vx[2];
        if (npw == 4) o[3] = vx[3];
    }
}

extern "C" void kernel_launch(void* const* d_in, const int* in_sizes, int n_in,
                              void* d_out, int out_size)
{
    const float* feat   = (const float*)d_in[0];
    const int*   rois32 = (const int*)d_in[1];
    float*       out    = (float*)d_out;

    dim3 tgrid((RP_P + 127) / 128, RP_C / 32, RP_B);   // 20 x 8 x 4
    transpose_kernel<<<tgrid, 256>>>(feat);

    dim3 pgrid(RP_R, RP_PH);                            // 256 x 7
    roipool5_kernel<<<pgrid, 128>>>(rois32, out);
}